// round 16
// baseline (speedup 1.0000x reference)
#include <cuda_runtime.h>
#include <math.h>

#define KK   8
#define H    250
#define HP   252
#define NP   56
#define HA_  100
#define MM   576
#define NB   2048
#define BK   (NB*KK)
#define CIN  1076
#define EPS_ 1e-5f
#define K2E  125
#define K2C  250
#define KP   1080
#define NPAD2 256

typedef unsigned long long u64t;

__device__ __forceinline__ u64t pack2(float lo, float hi) {
    u64t r;
    asm("mov.b64 %0, {%1, %2};" : "=l"(r) : "f"(lo), "f"(hi));
    return r;
}
__device__ __forceinline__ void fma2(u64t& d, u64t a, u64t b) {
    asm("fma.rn.f32x2 %0, %1, %2, %0;" : "+l"(d) : "l"(a), "l"(b));
}
__device__ __forceinline__ float sum2(u64t v) {
    float lo, hi;
    asm("mov.b64 {%0, %1}, %2;" : "=f"(lo), "=f"(hi) : "l"(v));
    return lo + hi;
}
__device__ __forceinline__ float tf32r(float f) {
    unsigned u;
    asm("cvt.rna.tf32.f32 %0, %1;" : "=r"(u) : "f"(f));
    return __uint_as_float(u);
}

#define MMA_TF32(D, A, B0, B1) \
    asm volatile("mma.sync.aligned.m16n8k8.row.col.f32.tf32.tf32.f32 " \
        "{%0,%1,%2,%3}, {%4,%5,%6,%7}, {%8,%9}, {%0,%1,%2,%3};" \
        : "+f"((D)[0]), "+f"((D)[1]), "+f"((D)[2]), "+f"((D)[3]) \
        : "r"((A)[0]), "r"((A)[1]), "r"((A)[2]), "r"((A)[3]), "r"(B0), "r"(B1))

// scratch + packed weights (allocation-free rule: device globals)
__device__ float g_s1 [(size_t)BK * H];
__device__ float g_eff[(size_t)BK * H];
__device__ u64t  g_Wenc [K2E * H];
__device__ u64t  g_Wcore[K2C * H];
__device__ u64t  g_Wctx [K2E * H];      // pre-multiplied by core_g (LN fold)
__device__ u64t  g_Watt [K2E * HA_];    // pre-multiplied by core_g (LN fold)
__device__ float g_t1c[H],  g_t2c[H];
__device__ float g_t1a[HA_], g_t2a[HA_];
// mma weight hi/lo planes (B side only; A converted in-kernel)
__device__ float g_WHp [KP * NPAD2];
__device__ float g_WLp [KP * NPAD2];

// ---------------------------------------------------------------------------
// ONE prep kernel: pack enc/core/ctx/att (+LN folds), wpad hi/lo, t-vectors.
// ---------------------------------------------------------------------------
#define N_E (K2E*H)
#define N_C (K2C*H)
#define N_A (K2E*HA_)
#define N_PACK (N_E + N_C + N_E + N_A)
#define N_WPAD (KP * NPAD2)
#define N_PREP (N_PACK + N_WPAD + H + HA_)
__global__ void prep_all(const float* __restrict__ encW, const float* __restrict__ coreW,
                         const float* __restrict__ ctxW, const float* __restrict__ attW,
                         const float* __restrict__ outW,
                         const float* __restrict__ core_g, const float* __restrict__ core_bt,
                         const float* __restrict__ ctx_b,  const float* __restrict__ att_b1) {
    int i = blockIdx.x * 256 + threadIdx.x;
    if (i < N_E) {
        int k2 = i / H, c = i - k2 * H;
        g_Wenc[i] = pack2(encW[(2 * k2) * H + c], encW[(2 * k2 + 1) * H + c]);
        return;
    }
    i -= N_E;
    if (i < N_C) {
        int k2 = i / H, c = i - k2 * H;
        g_Wcore[i] = pack2(coreW[(2 * k2) * H + c], coreW[(2 * k2 + 1) * H + c]);
        return;
    }
    i -= N_C;
    if (i < N_E) {
        int k2 = i / H, c = i - k2 * H;
        g_Wctx[i] = pack2(core_g[2 * k2]     * ctxW[(2 * k2) * H + c],
                          core_g[2 * k2 + 1] * ctxW[(2 * k2 + 1) * H + c]);
        return;
    }
    i -= N_E;
    if (i < N_A) {
        int k2 = i / HA_, c = i - k2 * HA_;
        g_Watt[i] = pack2(core_g[2 * k2]     * attW[(2 * k2) * HA_ + c],
                          core_g[2 * k2 + 1] * attW[(2 * k2 + 1) * HA_ + c]);
        return;
    }
    i -= N_A;
    if (i < N_WPAD) {
        int k = i / NPAD2, n = i - k * NPAD2;
        float v = (k < CIN && n < H) ? outW[(size_t)k * H + n] : 0.f;
        float hi = tf32r(v);
        g_WHp[i] = hi;
        g_WLp[i] = tf32r(v - hi);
        return;
    }
    i -= N_WPAD;
    if (i < H) {
        float t1 = 0.f, t2 = 0.f;
        #pragma unroll 4
        for (int c = 0; c < H; c++) {
            float w = ctxW[(size_t)c * H + i];
            t1 += w * core_bt[c];
            t2 += w * core_g[c];
        }
        g_t1c[i] = t1 + ctx_b[i];
        g_t2c[i] = t2;
        return;
    }
    i -= H;
    if (i < HA_) {
        float t1 = 0.f, t2 = 0.f;
        #pragma unroll 4
        for (int c = 0; c < H; c++) {
            float w = attW[(size_t)c * HA_ + i];
            t1 += w * core_bt[c];
            t2 += w * core_g[c];
        }
        g_t1a[i] = t1 + att_b1[i];
        g_t2a[i] = t2;
    }
}

// ---------------------------------------------------------------------------
// shared FFMA2 GEMM helpers
// ---------------------------------------------------------------------------
template<int NR>
__device__ __forceinline__ void chunk_body(
    u64t* a0, u64t* a1, const float* base, int rowstride, int k,
    const u64t* wa0, const u64t* wa1)
{
    #pragma unroll
    for (int e = 0; e < NR; e++) {
        ulonglong2 v0 = *(const ulonglong2*)&base[e * rowstride + k];
        ulonglong2 v1 = *(const ulonglong2*)&base[e * rowstride + k + 4];
        fma2(a0[e], v0.x, wa0[0]); fma2(a0[e], v0.y, wa0[1]);
        fma2(a0[e], v1.x, wa0[2]); fma2(a0[e], v1.y, wa0[3]);
        fma2(a1[e], v0.x, wa1[0]); fma2(a1[e], v0.y, wa1[1]);
        fma2(a1[e], v1.x, wa1[2]); fma2(a1[e], v1.y, wa1[3]);
    }
}
// single-column variant (enc prologue)
template<int NR>
__device__ __forceinline__ void chunk_body1(
    u64t* a, const float* base, int rowstride, int k, const u64t* w)
{
    #pragma unroll
    for (int e = 0; e < NR; e++) {
        ulonglong2 v0 = *(const ulonglong2*)&base[e * rowstride + k];
        ulonglong2 v1 = *(const ulonglong2*)&base[e * rowstride + k + 4];
        fma2(a[e], v0.x, w[0]); fma2(a[e], v0.y, w[1]);
        fma2(a[e], v1.x, w[2]); fma2(a[e], v1.y, w[3]);
    }
}
__device__ __forceinline__ void ldw4(u64t* w0, u64t* w1,
                                     const u64t* W0, const u64t* W1,
                                     int k2, int stride) {
    #pragma unroll
    for (int j = 0; j < 4; j++) {
        w0[j] = W0[(size_t)(k2 + j) * stride];
        w1[j] = W1[(size_t)(k2 + j) * stride];
    }
}
__device__ __forceinline__ void cpw4(u64t* wa0, u64t* wa1,
                                     const u64t* wb0, const u64t* wb1) {
    #pragma unroll
    for (int j = 0; j < 4; j++) { wa0[j] = wb0[j]; wa1[j] = wb1[j]; }
}

// ---------------------------------------------------------------------------
// Kernel 2: fused enc + pair pipeline, 512 threads.
// ---------------------------------------------------------------------------
__global__ __launch_bounds__(512, 1) void pair_kernel(
    const float* __restrict__ state,
    const float* __restrict__ enc_b,  const float* __restrict__ enc_g,
    const float* __restrict__ enc_bt,
    const float* __restrict__ core_b,
    const float* __restrict__ ctx_g,  const float* __restrict__ ctx_bt,
    const float* __restrict__ att_g,  const float* __restrict__ att_bt,
    const float* __restrict__ att_W2, const float* __restrict__ att_b2)
{
    extern __shared__ float sm[];
    float* s1s   = sm;                    // 8  * HP  (s1, post-LN)
    float* fbufA = s1s   + KK * HP;       // partial buffers / enc staging
    float* fbufB = fbufA + KK * HP;
    float* obufA = fbufB + KK * HP;
    float* obufB = obufA + KK * HP;
    float* coreb = obufB + KK * HP;       // 56 * HP (raw, post-relu)
    float* ctxb  = coreb + NP * HP;       // 56 * HP (raw, post-relu)
    float* attb  = ctxb  + NP * HP;       // 56 * HA_
    float* attv  = attb  + NP * HA_;      // 56 (enc-LN scratch first, attv later)
    float* stA   = attv  + NP;            // 56*2  (mu*rs, rs) of coreb
    float* stC   = stA   + NP * 2;        // 56*2  (mu*rs, rs) of ctxb

    const int t = threadIdx.x;
    const int grp = blockIdx.x;
    const int warp = t >> 5, lane = t & 31;

    const int qg = t >> 7, u = t & 127;
    const int c0 = u, c1 = u + 128;
    const int c1ok = (c1 < H);
    const int c1v = c1ok ? c1 : 0;

    // ================= fused enc: s1 = LN(relu(state @ enc_W + b)) =========
    // E0: stage state rows into fbufA
    for (int i = t; i < KK * H; i += 512) {
        int r = i / H, c = i - r * H;
        fbufA[r * HP + c] = state[((size_t)grp * KK + r) * H + c];
    }
    __syncthreads();

    // E1: enc GEMM, two k2-halves (0..63 | 64..124), 1 col x 8 rows / thread
    {
        const int kh = t >> 8;
        const int c = t & 255;
        if (c < H) {
            const u64t* W = g_Wenc + c;
            u64t a[8];
            #pragma unroll
            for (int e = 0; e < 8; e++) a[e] = 0ull;

            const int k2s = kh ? 64 : 0;
            const int nch = kh ? 15 : 16;
            u64t wa[4], wb[4];
            #pragma unroll
            for (int j = 0; j < 4; j++) wa[j] = W[(size_t)(k2s + j) * H];
            #pragma unroll 1
            for (int i2 = 0; i2 < nch; i2++) {
                if (i2 + 1 < nch) {
                    #pragma unroll
                    for (int j = 0; j < 4; j++)
                        wb[j] = W[(size_t)(k2s + 4 * (i2 + 1) + j) * H];
                }
                chunk_body1<8>(a, fbufA, HP, 2 * (k2s + 4 * i2), wa);
                #pragma unroll
                for (int j = 0; j < 4; j++) wa[j] = wb[j];
            }
            if (kh) {   // tail k2 = 124 (k = 248,249)
                u64t wt = W[(size_t)124 * H];
                #pragma unroll
                for (int e = 0; e < 8; e++) {
                    u64t v = *(const u64t*)&fbufA[e * HP + 248];
                    fma2(a[e], v, wt);
                }
            }
            float* pd = kh ? obufA : fbufB;
            #pragma unroll
            for (int e = 0; e < 8; e++) pd[e * HP + c] = sum2(a[e]);
        }
    }
    __syncthreads();

    // E2: merged relu + LN stats (warps 0..7, one row each); stats in attv[0..15]
    if (warp < 8) {
        const int r = warp;
        float s = 0.f, s2 = 0.f;
        for (int c = lane; c < H; c += 32) {
            float v = fmaxf(fbufB[r * HP + c] + obufA[r * HP + c] + enc_b[c], 0.f);
            s1s[r * HP + c] = v;
            s += v; s2 += v * v;
        }
        #pragma unroll
        for (int off = 16; off; off >>= 1) {
            s  += __shfl_xor_sync(0xffffffffu, s,  off);
            s2 += __shfl_xor_sync(0xffffffffu, s2, off);
        }
        if (lane == 0) {
            float mu = s * (1.f / H);
            attv[2 * r]     = mu;
            attv[2 * r + 1] = rsqrtf(s2 * (1.f / H) - mu * mu + EPS_);
        }
    }
    __syncthreads();

    // E3: normalize in smem + store to global (for out_mma)
    {
        const int kh = t >> 8;
        const int c = t & 255;
        if (c < H) {
            float gg = enc_g[c], bb = enc_bt[c];
            #pragma unroll
            for (int rr = 0; rr < 4; rr++) {
                const int r = kh * 4 + rr;
                float v = (s1s[r * HP + c] - attv[2 * r]) * attv[2 * r + 1] * gg + bb;
                s1s[r * HP + c] = v;
                g_s1[((size_t)grp * KK + r) * H + c] = v;
            }
        }
    }
    __syncthreads();

    // ================= pair pipeline (R15 body) =============================
    // ---- core GEMM: quadrant = (k-half, focal/other); 2 cols per thread ----
    {
        const int wh = qg & 1;
        const int kh = qg >> 1;
        const u64t* W0 = g_Wcore + (size_t)(wh * 125) * H + c0;
        const u64t* W1 = g_Wcore + (size_t)(wh * 125) * H + c1v;
        u64t a0[8], a1[8];
        #pragma unroll
        for (int e = 0; e < 8; e++) { a0[e] = 0ull; a1[e] = 0ull; }

        int kc = kh ? 64 : 0;
        const int kstop = kh ? 120 : 60;
        u64t wa0[4], wa1[4];
        ldw4(wa0, wa1, W0, W1, kc, H);
        #pragma unroll 1
        for (; kc < kstop; kc += 4) {
            u64t wb0[4], wb1[4];
            ldw4(wb0, wb1, W0, W1, kc + 4, H);
            chunk_body<8>(a0, a1, s1s, HP, 2 * kc, wa0, wa1);
            cpw4(wa0, wa1, wb0, wb1);
        }
        chunk_body<8>(a0, a1, s1s, HP, 2 * kstop, wa0, wa1);
        if (kh) {
            u64t wt0 = W0[(size_t)124 * H], wt1 = W1[(size_t)124 * H];
            #pragma unroll
            for (int e = 0; e < 8; e++) {
                u64t v = *(const u64t*)&s1s[e * HP + 248];
                fma2(a0[e], v, wt0);
                fma2(a1[e], v, wt1);
            }
        }
        float* fd = kh ? (wh ? obufB : fbufB) : (wh ? obufA : fbufA);
        #pragma unroll
        for (int e = 0; e < 8; e++) {
            fd[e * HP + c0] = sum2(a0[e]);
            if (c1ok) fd[e * HP + c1] = sum2(a1[e]);
        }
    }
    __syncthreads();

    // ---- merged assemble + LN stats (warp per pair; division-free) ----
    for (int p = warp; p < NP; p += 16) {
        const int fi = (p * 9363) >> 16;        // p / 7
        const int jj = p - fi * 7;
        const int o = jj + (jj >= fi);
        const float* fA = fbufA + fi * HP;
        const float* fB = fbufB + fi * HP;
        const float* oA = obufA + o * HP;
        const float* oB = obufB + o * HP;
        float s = 0.f, s2 = 0.f;
        for (int c = lane; c < H; c += 32) {
            float v = fmaxf(fA[c] + fB[c] + oA[c] + oB[c] + core_b[c], 0.f);
            coreb[p * HP + c] = v;
            s += v; s2 += v * v;
        }
        #pragma unroll
        for (int off = 16; off; off >>= 1) {
            s  += __shfl_xor_sync(0xffffffffu, s,  off);
            s2 += __shfl_xor_sync(0xffffffffu, s2, off);
        }
        if (lane == 0) {
            float mu = s * (1.f / H);
            float rs = rsqrtf(s2 * (1.f / H) - mu * mu + EPS_);
            stA[2 * p]     = mu * rs;
            stA[2 * p + 1] = rs;
        }
    }
    __syncthreads();

    // ---- ctx GEMM over RAW coreb with folded weights; LN in epilogue ----
    {
        const int pbase = qg * 14;
        const u64t* W0 = g_Wctx + c0;
        const u64t* W1 = g_Wctx + c1v;
        u64t a0[14], a1[14];
        #pragma unroll
        for (int pp = 0; pp < 14; pp++) { a0[pp] = 0ull; a1[pp] = 0ull; }

        u64t wa0[2], wa1[2];
        wa0[0] = W0[0]; wa0[1] = W0[H];
        wa1[0] = W1[0]; wa1[1] = W1[H];
        #pragma unroll 2
        for (int kc2 = 0; kc2 < 122; kc2 += 2) {
            u64t wb0[2], wb1[2];
            wb0[0] = W0[(size_t)(kc2 + 2) * H]; wb0[1] = W0[(size_t)(kc2 + 3) * H];
            wb1[0] = W1[(size_t)(kc2 + 2) * H]; wb1[1] = W1[(size_t)(kc2 + 3) * H];
            const int k = 2 * kc2;
            #pragma unroll
            for (int pp = 0; pp < 14; pp++) {
                ulonglong2 v = *(const ulonglong2*)&coreb[(pbase + pp) * HP + k];
                fma2(a0[pp], v.x, wa0[0]); fma2(a0[pp], v.y, wa0[1]);
                fma2(a1[pp], v.x, wa1[0]); fma2(a1[pp], v.y, wa1[1]);
            }
            wa0[0] = wb0[0]; wa0[1] = wb0[1];
            wa1[0] = wb1[0]; wa1[1] = wb1[1];
        }
        {
            #pragma unroll
            for (int pp = 0; pp < 14; pp++) {
                ulonglong2 v = *(const ulonglong2*)&coreb[(pbase + pp) * HP + 244];
                fma2(a0[pp], v.x, wa0[0]); fma2(a0[pp], v.y, wa0[1]);
                fma2(a1[pp], v.x, wa1[0]); fma2(a1[pp], v.y, wa1[1]);
            }
        }
        {
            u64t wt0 = W0[(size_t)124 * H], wt1 = W1[(size_t)124 * H];
            #pragma unroll
            for (int pp = 0; pp < 14; pp++) {
                u64t v = *(const u64t*)&coreb[(pbase + pp) * HP + 248];
                fma2(a0[pp], v, wt0);
                fma2(a1[pp], v, wt1);
            }
        }
        const float t10 = g_t1c[c0], t20 = g_t2c[c0];
        const float t11 = g_t1c[c1v], t21 = g_t2c[c1v];
        #pragma unroll
        for (int pp = 0; pp < 14; pp++) {
            const int p = pbase + pp;
            const float ms = stA[2 * p], rs = stA[2 * p + 1];
            ctxb[p * HP + c0] = fmaxf(rs * sum2(a0[pp]) - ms * t20 + t10, 0.f);
            if (c1ok)
                ctxb[p * HP + c1] = fmaxf(rs * sum2(a1[pp]) - ms * t21 + t11, 0.f);
        }
    }

    // ---- att1 GEMM over RAW coreb (folded); 8 groups x 7 pairs x 2 cols ----
    {
        const int g8 = t >> 6, u6 = t & 63;
        if (u6 < 50) {
            const int pbase = g8 * 7;
            const int ac0 = u6, ac1 = u6 + 50;
            const u64t* W0 = g_Watt + ac0;
            const u64t* W1 = g_Watt + ac1;
            u64t a0[7], a1[7];
            #pragma unroll
            for (int pp = 0; pp < 7; pp++) { a0[pp] = 0ull; a1[pp] = 0ull; }

            u64t wa0[4], wa1[4];
            ldw4(wa0, wa1, W0, W1, 0, HA_);
            #pragma unroll 2
            for (int kc = 0; kc < 120; kc += 4) {
                u64t wb0[4], wb1[4];
                ldw4(wb0, wb1, W0, W1, kc + 4, HA_);
                chunk_body<7>(a0, a1, coreb + pbase * HP, HP, 2 * kc, wa0, wa1);
                cpw4(wa0, wa1, wb0, wb1);
            }
            chunk_body<7>(a0, a1, coreb + pbase * HP, HP, 240, wa0, wa1);
            {
                u64t wt0 = W0[(size_t)124 * HA_], wt1 = W1[(size_t)124 * HA_];
                #pragma unroll
                for (int pp = 0; pp < 7; pp++) {
                    u64t v = *(const u64t*)&coreb[(pbase + pp) * HP + 248];
                    fma2(a0[pp], v, wt0);
                    fma2(a1[pp], v, wt1);
                }
            }
            const float t10 = g_t1a[ac0], t20 = g_t2a[ac0];
            const float t11 = g_t1a[ac1], t21 = g_t2a[ac1];
            #pragma unroll
            for (int pp = 0; pp < 7; pp++) {
                const int p = pbase + pp;
                const float ms = stA[2 * p], rs = stA[2 * p + 1];
                attb[p * HA_ + ac0] = tanhf(rs * sum2(a0[pp]) - ms * t20 + t10);
                attb[p * HA_ + ac1] = tanhf(rs * sum2(a1[pp]) - ms * t21 + t11);
            }
        }
    }
    __syncthreads();

    // ---- ctx LN stats + att LN + att2 + sigmoid (warp per pair) ----
    for (int p = warp; p < NP; p += 16) {
        {
            float s = 0.f, s2 = 0.f;
            for (int k = lane; k < H; k += 32) {
                float v = ctxb[p * HP + k];
                s += v; s2 += v * v;
            }
            #pragma unroll
            for (int off = 16; off; off >>= 1) {
                s  += __shfl_xor_sync(0xffffffffu, s,  off);
                s2 += __shfl_xor_sync(0xffffffffu, s2, off);
            }
            if (lane == 0) {
                float mu = s * (1.f / H);
                float rs = rsqrtf(s2 * (1.f / H) - mu * mu + EPS_);
                stC[2 * p]     = mu * rs;
                stC[2 * p + 1] = rs;
            }
        }
        {
            float s = 0.f, s2 = 0.f;
            for (int k = lane; k < HA_; k += 32) {
                float v = attb[p * HA_ + k];
                s += v; s2 += v * v;
            }
            #pragma unroll
            for (int off = 16; off; off >>= 1) {
                s  += __shfl_xor_sync(0xffffffffu, s,  off);
                s2 += __shfl_xor_sync(0xffffffffu, s2, off);
            }
            float mu = s * (1.f / HA_);
            float rs = rsqrtf(s2 * (1.f / HA_) - mu * mu + EPS_);
            float s3 = 0.f;
            for (int k = lane; k < HA_; k += 32) {
                float v = (attb[p * HA_ + k] - mu) * rs * att_g[k] + att_bt[k];
                s3 += v * att_W2[k];
            }
            #pragma unroll
            for (int off = 16; off; off >>= 1)
                s3 += __shfl_xor_sync(0xffffffffu, s3, off);
            if (lane == 0)
                attv[p] = 1.f / (1.f + expf(-(s3 + att_b2[0])));
        }
    }
    __syncthreads();

    // ---- effect (folded ctx-LN) ----
    {
        const int c = t & 255, eh = t >> 8;
        if (c < H) {
            const float cgc = ctx_g[c], cbtc = ctx_bt[c];
            #pragma unroll
            for (int e4 = 0; e4 < 4; e4++) {
                const int e = eh * 4 + e4;
                float acc = 0.f, A = 0.f, Bs = 0.f;
                #pragma unroll
                for (int j = 0; j < 7; j++) {
                    const int p = e * 7 + j;
                    const float av = attv[p];
                    const float w  = av * stC[2 * p + 1];
                    acc += w * ctxb[p * HP + c];
                    A   += av;
                    Bs  += av * stC[2 * p];
                }
                g_eff[((size_t)grp * KK + e) * H + c] = cgc * (acc - Bs) + A * cbtc;
            }
        }
    }
}

// ---------------------------------------------------------------------------
// Kernel 3: out GEMM via tf32 mma.sync (3xTF32), concat fused into A-load.
// ---------------------------------------------------------------------------
__device__ __forceinline__ float load_tot(const float* __restrict__ x, int row, int k) {
    if (k < H)          return g_s1[(size_t)row * H + k];
    if (k < 2 * H)      return g_eff[(size_t)row * H + (k - H)];
    if (k < CIN)        return x[(size_t)row * MM + (k - 2 * H)];
    return 0.f;
}

#define LOAD_STAGE(s, k0) do {                                                        \
    {   /* A: gather [s1|eff|x] + tf32 hi/lo split in-register */                     \
        const int row = m0 + am;                                                      \
        float v0 = load_tot(x, row, (k0) + ak);                                       \
        float v1 = load_tot(x, row, (k0) + ak + 1);                                   \
        float h0 = tf32r(v0), h1 = tf32r(v1);                                         \
        AsH[s][am * 8 + ak]     = h0;                                                 \
        AsH[s][am * 8 + ak + 1] = h1;                                                 \
        AsL[s][am * 8 + ak]     = tf32r(v0 - h0);                                     \
        AsL[s][am * 8 + ak + 1] = tf32r(v1 - h1);                                     \
    }                                                                                 \
    {   /* B: precomputed hi/lo planes */                                             \
        const float* wh = &g_WHp[(size_t)((k0) + bk) * NPAD2 + bn];                   \
        const float* wl = &g_WLp[(size_t)((k0) + bk) * NPAD2 + bn];                   \
        *(float4*)&BsH[s][bk * 260 + bn]     = *(const float4*)wh;                    \
        *(float4*)&BsH[s][bk * 260 + bn + 4] = *(const float4*)(wh + 4);              \
        *(float4*)&BsL[s][bk * 260 + bn]     = *(const float4*)wl;                    \
        *(float4*)&BsL[s][bk * 260 + bn + 4] = *(const float4*)(wl + 4);              \
    }                                                                                 \
} while (0)

__global__ __launch_bounds__(256, 2) void out_mma_kernel(
    const float* __restrict__ x,
    const float* __restrict__ bias, float* __restrict__ out)
{
    __shared__ float AsH[2][64 * 8], AsL[2][64 * 8];
    __shared__ float BsH[2][8 * 260], BsL[2][8 * 260];

    const int t = threadIdx.x;
    const int m0 = blockIdx.x * 64;
    const int w = t >> 5, lane = t & 31;
    const int wm = w & 1, wn = w >> 1;
    const int gid = lane >> 2, ctid = lane & 3;

    const int am = t >> 2;              // A row 0..63
    const int ak = (t & 3) * 2;         // A k-pair within 8
    const int bk = t >> 5;              // B k row 0..7
    const int bn = (t & 31) * 8;        // B n 0..248

    float d[2][8][4];
    #pragma unroll
    for (int mf = 0; mf < 2; mf++)
        #pragma unroll
        for (int nf = 0; nf < 8; nf++)
            #pragma unroll
            for (int q = 0; q < 4; q++) d[mf][nf][q] = 0.f;

    LOAD_STAGE(0, 0);

    #pragma unroll 1
    for (int ks = 0; ks < 135; ks++) {
        const int s = ks & 1;
        __syncthreads();
        if (ks + 1 < 135) LOAD_STAGE(s ^ 1, (ks + 1) * 8);

        unsigned aH[2][4], aL[2][4];
        #pragma unroll
        for (int mf = 0; mf < 2; mf++) {
            const int rb = wm * 32 + mf * 16;
            aH[mf][0] = __float_as_uint(AsH[s][(rb + gid) * 8 + ctid]);
            aH[mf][1] = __float_as_uint(AsH[s][(rb + gid + 8) * 8 + ctid]);
            aH[mf][2] = __float_as_uint(AsH[s][(rb + gid) * 8 + ctid + 4]);
            aH[mf][3] = __float_as_uint(AsH[s][(rb + gid + 8) * 8 + ctid + 4]);
            aL[mf][0] = __float_as_uint(AsL[s][(rb + gid) * 8 + ctid]);
            aL[mf][1] = __float_as_uint(AsL[s][(rb + gid + 8) * 8 + ctid]);
            aL[mf][2] = __float_as_uint(AsL[s][(rb + gid) * 8 + ctid + 4]);
            aL[mf][3] = __float_as_uint(AsL[s][(rb + gid + 8) * 8 + ctid + 4]);
        }
        #pragma unroll
        for (int nf = 0; nf < 8; nf++) {
            const int n = wn * 64 + nf * 8 + gid;
            unsigned bH0 = __float_as_uint(BsH[s][ctid * 260 + n]);
            unsigned bH1 = __float_as_uint(BsH[s][(ctid + 4) * 260 + n]);
            unsigned bL0 = __float_as_uint(BsL[s][ctid * 260 + n]);
            unsigned bL1 = __float_as_uint(BsL[s][(ctid + 4) * 260 + n]);
            #pragma unroll
            for (int mf = 0; mf < 2; mf++) {
                MMA_TF32(d[mf][nf], aH[mf], bH0, bH1);
                MMA_TF32(d[mf][nf], aL[mf], bH0, bH1);
                MMA_TF32(d[mf][nf], aH[mf], bL0, bL1);
            }
        }
    }

    #pragma unroll
    for (int mf = 0; mf < 2; mf++) {
        const int r0 = m0 + wm * 32 + mf * 16 + gid;
        #pragma unroll
        for (int nf = 0; nf < 8; nf++) {
            const int n = wn * 64 + nf * 8 + 2 * ctid;
            if (n < H) {
                float b0 = bias[n], b1 = bias[n + 1];
                out[(size_t)r0 * H + n]           = d[mf][nf][0] + b0;
                out[(size_t)r0 * H + n + 1]       = d[mf][nf][1] + b1;
                out[(size_t)(r0 + 8) * H + n]     = d[mf][nf][2] + b0;
                out[(size_t)(r0 + 8) * H + n + 1] = d[mf][nf][3] + b1;
            }
        }
    }
}

// ---------------------------------------------------------------------------
extern "C" void kernel_launch(void* const* d_in, const int* in_sizes, int n_in,
                              void* d_out, int out_size)
{
    const float* x       = (const float*)d_in[0];
    const float* state   = (const float*)d_in[1];
    const float* enc_W   = (const float*)d_in[2];
    const float* enc_b   = (const float*)d_in[3];
    const float* enc_g   = (const float*)d_in[4];
    const float* enc_bt  = (const float*)d_in[5];
    const float* core_W  = (const float*)d_in[6];
    const float* core_b  = (const float*)d_in[7];
    const float* core_g  = (const float*)d_in[8];
    const float* core_bt = (const float*)d_in[9];
    const float* ctx_W   = (const float*)d_in[10];
    const float* ctx_b   = (const float*)d_in[11];
    const float* ctx_g   = (const float*)d_in[12];
    const float* ctx_bt  = (const float*)d_in[13];
    const float* att_W1  = (const float*)d_in[14];
    const float* att_b1  = (const float*)d_in[15];
    const float* att_g   = (const float*)d_in[16];
    const float* att_bt  = (const float*)d_in[17];
    const float* att_W2  = (const float*)d_in[18];
    const float* att_b2  = (const float*)d_in[19];
    const float* out_W   = (const float*)d_in[20];
    const float* out_b   = (const float*)d_in[21];
    float* out = (float*)d_out;

    static int configured = 0;
    const int pair_smB = (5 * KK * HP + 2 * NP * HP + NP * HA_ + NP + 4 * NP) * (int)sizeof(float);
    if (!configured) {
        cudaFuncSetAttribute(pair_kernel, cudaFuncAttributeMaxDynamicSharedMemorySize, pair_smB);
        configured = 1;
    }

    prep_all<<<(N_PREP + 255) / 256, 256>>>(enc_W, core_W, ctx_W, att_W1, out_W,
                                            core_g, core_bt, ctx_b, att_b1);
    pair_kernel<<<NB, 512, pair_smB>>>(state, enc_b, enc_g, enc_bt,
                                       core_b, ctx_g, ctx_bt,
                                       att_g, att_bt, att_W2, att_b2);
    out_mma_kernel<<<BK / 64, 256>>>(x, out_b, out);
}

// round 17
// speedup vs baseline: 1.0285x; 1.0285x over previous
#include <cuda_runtime.h>
#include <math.h>

#define KK   8
#define H    250
#define HP   252
#define NP   56
#define HA_  100
#define MM   576
#define NB   2048
#define BK   (NB*KK)
#define CIN  1076
#define EPS_ 1e-5f
#define K2E  125
#define K2C  250
#define KP   1080
#define NPAD2 256

typedef unsigned long long u64t;

__device__ __forceinline__ u64t pack2(float lo, float hi) {
    u64t r;
    asm("mov.b64 %0, {%1, %2};" : "=l"(r) : "f"(lo), "f"(hi));
    return r;
}
__device__ __forceinline__ void fma2(u64t& d, u64t a, u64t b) {
    asm("fma.rn.f32x2 %0, %1, %2, %0;" : "+l"(d) : "l"(a), "l"(b));
}
__device__ __forceinline__ float sum2(u64t v) {
    float lo, hi;
    asm("mov.b64 {%0, %1}, %2;" : "=f"(lo), "=f"(hi) : "l"(v));
    return lo + hi;
}
__device__ __forceinline__ float tf32r(float f) {
    unsigned u;
    asm("cvt.rna.tf32.f32 %0, %1;" : "=r"(u) : "f"(f));
    return __uint_as_float(u);
}

#define MMA_TF32(D, A, B0, B1) \
    asm volatile("mma.sync.aligned.m16n8k8.row.col.f32.tf32.tf32.f32 " \
        "{%0,%1,%2,%3}, {%4,%5,%6,%7}, {%8,%9}, {%0,%1,%2,%3};" \
        : "+f"((D)[0]), "+f"((D)[1]), "+f"((D)[2]), "+f"((D)[3]) \
        : "r"((A)[0]), "r"((A)[1]), "r"((A)[2]), "r"((A)[3]), "r"(B0), "r"(B1))

// scratch + packed weights (allocation-free rule: device globals)
__device__ float g_s1 [(size_t)BK * H];
__device__ float g_eff[(size_t)BK * H];
__device__ u64t  g_Wenc [K2E * H];
__device__ u64t  g_Wcore[K2C * H];
__device__ u64t  g_Wctx [K2E * H];      // pre-multiplied by core_g (LN fold)
__device__ u64t  g_Watt [K2E * HA_];    // pre-multiplied by core_g (LN fold)
__device__ float g_t1c[H],  g_t2c[H];
__device__ float g_t1a[HA_], g_t2a[HA_];
__device__ float g_gw2[HA_];            // att_g * att_W2 (att-LN fold)
__device__ float g_Sgw, g_Sbw;          // Σ att_g*W2, Σ att_bt*W2
// mma weight hi/lo planes (B side only; A converted in-kernel)
__device__ float g_WHp [KP * NPAD2];
__device__ float g_WLp [KP * NPAD2];

// ---------------------------------------------------------------------------
// ONE prep kernel: pack weights (+LN folds), wpad hi/lo, t-vectors, att fold.
// ---------------------------------------------------------------------------
#define N_E (K2E*H)
#define N_C (K2C*H)
#define N_A (K2E*HA_)
#define N_PACK (N_E + N_C + N_E + N_A)
#define N_WPAD (KP * NPAD2)
#define N_PREP (N_PACK + N_WPAD + H + HA_ + HA_ + 1)
__global__ void prep_all(const float* __restrict__ encW, const float* __restrict__ coreW,
                         const float* __restrict__ ctxW, const float* __restrict__ attW,
                         const float* __restrict__ outW,
                         const float* __restrict__ core_g, const float* __restrict__ core_bt,
                         const float* __restrict__ ctx_b,  const float* __restrict__ att_b1,
                         const float* __restrict__ att_g,  const float* __restrict__ att_bt,
                         const float* __restrict__ att_W2) {
    int i = blockIdx.x * 256 + threadIdx.x;
    if (i < N_E) {
        int k2 = i / H, c = i - k2 * H;
        g_Wenc[i] = pack2(encW[(2 * k2) * H + c], encW[(2 * k2 + 1) * H + c]);
        return;
    }
    i -= N_E;
    if (i < N_C) {
        int k2 = i / H, c = i - k2 * H;
        g_Wcore[i] = pack2(coreW[(2 * k2) * H + c], coreW[(2 * k2 + 1) * H + c]);
        return;
    }
    i -= N_C;
    if (i < N_E) {
        int k2 = i / H, c = i - k2 * H;
        g_Wctx[i] = pack2(core_g[2 * k2]     * ctxW[(2 * k2) * H + c],
                          core_g[2 * k2 + 1] * ctxW[(2 * k2 + 1) * H + c]);
        return;
    }
    i -= N_E;
    if (i < N_A) {
        int k2 = i / HA_, c = i - k2 * HA_;
        g_Watt[i] = pack2(core_g[2 * k2]     * attW[(2 * k2) * HA_ + c],
                          core_g[2 * k2 + 1] * attW[(2 * k2 + 1) * HA_ + c]);
        return;
    }
    i -= N_A;
    if (i < N_WPAD) {
        int k = i / NPAD2, n = i - k * NPAD2;
        float v = (k < CIN && n < H) ? outW[(size_t)k * H + n] : 0.f;
        float hi = tf32r(v);
        g_WHp[i] = hi;
        g_WLp[i] = tf32r(v - hi);
        return;
    }
    i -= N_WPAD;
    if (i < H) {
        float t1 = 0.f, t2 = 0.f;
        #pragma unroll 4
        for (int c = 0; c < H; c++) {
            float w = ctxW[(size_t)c * H + i];
            t1 += w * core_bt[c];
            t2 += w * core_g[c];
        }
        g_t1c[i] = t1 + ctx_b[i];
        g_t2c[i] = t2;
        return;
    }
    i -= H;
    if (i < HA_) {
        float t1 = 0.f, t2 = 0.f;
        #pragma unroll 4
        for (int c = 0; c < H; c++) {
            float w = attW[(size_t)c * HA_ + i];
            t1 += w * core_bt[c];
            t2 += w * core_g[c];
        }
        g_t1a[i] = t1 + att_b1[i];
        g_t2a[i] = t2;
        return;
    }
    i -= HA_;
    if (i < HA_) {
        g_gw2[i] = att_g[i] * att_W2[i];
        return;
    }
    i -= HA_;
    if (i == 0) {
        float sg = 0.f, sb = 0.f;
        for (int k = 0; k < HA_; k++) {
            sg += att_g[k] * att_W2[k];
            sb += att_bt[k] * att_W2[k];
        }
        g_Sgw = sg;
        g_Sbw = sb;
    }
}

// ---------------------------------------------------------------------------
// shared FFMA2 GEMM helpers
// ---------------------------------------------------------------------------
template<int NR>
__device__ __forceinline__ void chunk_body(
    u64t* a0, u64t* a1, const float* base, int rowstride, int k,
    const u64t* wa0, const u64t* wa1)
{
    #pragma unroll
    for (int e = 0; e < NR; e++) {
        ulonglong2 v0 = *(const ulonglong2*)&base[e * rowstride + k];
        ulonglong2 v1 = *(const ulonglong2*)&base[e * rowstride + k + 4];
        fma2(a0[e], v0.x, wa0[0]); fma2(a0[e], v0.y, wa0[1]);
        fma2(a0[e], v1.x, wa0[2]); fma2(a0[e], v1.y, wa0[3]);
        fma2(a1[e], v0.x, wa1[0]); fma2(a1[e], v0.y, wa1[1]);
        fma2(a1[e], v1.x, wa1[2]); fma2(a1[e], v1.y, wa1[3]);
    }
}
__device__ __forceinline__ void ldw4(u64t* w0, u64t* w1,
                                     const u64t* W0, const u64t* W1,
                                     int k2, int stride) {
    #pragma unroll
    for (int j = 0; j < 4; j++) {
        w0[j] = W0[(size_t)(k2 + j) * stride];
        w1[j] = W1[(size_t)(k2 + j) * stride];
    }
}
__device__ __forceinline__ void cpw4(u64t* wa0, u64t* wa1,
                                     const u64t* wb0, const u64t* wb1) {
    #pragma unroll
    for (int j = 0; j < 4; j++) { wa0[j] = wb0[j]; wa1[j] = wb1[j]; }
}

// ---------------------------------------------------------------------------
// Kernel 1: s1 = LN(relu(state @ enc_W + enc_b)); 32 rows / block, 512 thr.
// 4 row-groups x 128 lanes; each thread 8 rows x 2 cols. Same inner loop as
// the proven R15 enc — only the row tiling changed (weight reuse x2).
// ---------------------------------------------------------------------------
#define ER 32
__global__ __launch_bounds__(512, 1) void enc_kernel(
    const float* __restrict__ state, const float* __restrict__ b,
    const float* __restrict__ g, const float* __restrict__ bt)
{
    __shared__ float sst[ER * HP];
    __shared__ float st[ER * 2];

    const int t = threadIdx.x;
    const size_t base = (size_t)blockIdx.x * ER;
    const float* srow = state + base * H;

    for (int i = t; i < ER * H; i += 512) {
        int r = i / H, c = i - r * H;
        sst[r * HP + c] = srow[i];
    }
    __syncthreads();

    const int rg = t >> 7, u = t & 127;
    const int c0 = u, c1 = u + 128;
    const int c1ok = (c1 < H);
    const int c1v = c1ok ? c1 : 0;

    float relu0[8], relu1[8];
    {
        const u64t* W0 = g_Wenc + c0;
        const u64t* W1 = g_Wenc + c1v;
        const float* sr = sst + rg * 8 * HP;
        u64t a0[8], a1[8];
        #pragma unroll
        for (int e = 0; e < 8; e++) { a0[e] = 0ull; a1[e] = 0ull; }

        u64t wa0[4], wa1[4];
        ldw4(wa0, wa1, W0, W1, 0, H);
        #pragma unroll 2
        for (int kc = 0; kc < 120; kc += 4) {
            u64t wb0[4], wb1[4];
            ldw4(wb0, wb1, W0, W1, kc + 4, H);
            chunk_body<8>(a0, a1, sr, HP, 2 * kc, wa0, wa1);
            cpw4(wa0, wa1, wb0, wb1);
        }
        chunk_body<8>(a0, a1, sr, HP, 240, wa0, wa1);
        {
            u64t wt0 = W0[(size_t)124 * H], wt1 = W1[(size_t)124 * H];
            #pragma unroll
            for (int e = 0; e < 8; e++) {
                u64t v = *(const u64t*)&sr[e * HP + 248];
                fma2(a0[e], v, wt0);
                fma2(a1[e], v, wt1);
            }
        }
        float b0 = b[c0], b1 = b[c1v];
        #pragma unroll
        for (int e = 0; e < 8; e++) {
            relu0[e] = fmaxf(sum2(a0[e]) + b0, 0.f);
            relu1[e] = fmaxf(sum2(a1[e]) + b1, 0.f);
        }
    }
    __syncthreads();
    #pragma unroll
    for (int e = 0; e < 8; e++) {
        sst[(8 * rg + e) * HP + c0] = relu0[e];
        if (c1ok) sst[(8 * rg + e) * HP + c1] = relu1[e];
    }
    __syncthreads();

    const int warp = t >> 5, lane = t & 31;
    for (int r = warp; r < ER; r += 16) {
        float s = 0.f, s2 = 0.f;
        for (int k = lane; k < H; k += 32) {
            float v = sst[r * HP + k];
            s += v; s2 += v * v;
        }
        #pragma unroll
        for (int off = 16; off; off >>= 1) {
            s  += __shfl_xor_sync(0xffffffffu, s,  off);
            s2 += __shfl_xor_sync(0xffffffffu, s2, off);
        }
        if (lane == 0) {
            float mu = s * (1.f / H);
            st[r * 2]     = mu;
            st[r * 2 + 1] = rsqrtf(s2 * (1.f / H) - mu * mu + EPS_);
        }
    }
    __syncthreads();

    {
        float g0 = g[c0], bb0 = bt[c0];
        float g1 = g[c1v], bb1 = bt[c1v];
        #pragma unroll
        for (int e = 0; e < 8; e++) {
            int r = 8 * rg + e;
            g_s1[(base + r) * H + c0] = (relu0[e] - st[r * 2]) * st[r * 2 + 1] * g0 + bb0;
            if (c1ok)
                g_s1[(base + r) * H + c1] = (relu1[e] - st[r * 2]) * st[r * 2 + 1] * g1 + bb1;
        }
    }
}

// ---------------------------------------------------------------------------
// Kernel 2: fused pair pipeline (R13/R15 body; att epilogue single-pass fold)
// ---------------------------------------------------------------------------
__global__ __launch_bounds__(512, 1) void pair_kernel(
    const float* __restrict__ core_b,
    const float* __restrict__ ctx_g,  const float* __restrict__ ctx_bt,
    const float* __restrict__ att_b2)
{
    extern __shared__ float sm[];
    float* s1s   = sm;                    // 8  * HP
    float* fbufA = s1s   + KK * HP;
    float* fbufB = fbufA + KK * HP;
    float* obufA = fbufB + KK * HP;
    float* obufB = obufA + KK * HP;
    float* coreb = obufB + KK * HP;       // 56 * HP (raw, post-relu)
    float* ctxb  = coreb + NP * HP;       // 56 * HP (raw, post-relu)
    float* attb  = ctxb  + NP * HP;       // 56 * HA_
    float* attv  = attb  + NP * HA_;      // 56
    float* stA   = attv  + NP;            // 56*2  (mu*rs, rs) of coreb
    float* stC   = stA   + NP * 2;        // 56*2  (mu*rs, rs) of ctxb

    const int t = threadIdx.x;
    const int grp = blockIdx.x;
    const int warp = t >> 5, lane = t & 31;

    const int qg = t >> 7, u = t & 127;
    const int c0 = u, c1 = u + 128;
    const int c1ok = (c1 < H);
    const int c1v = c1ok ? c1 : 0;

    for (int i = t; i < KK * H; i += 512) {
        int r = i / H, c = i - r * H;
        s1s[r * HP + c] = g_s1[((size_t)grp * KK + r) * H + c];
    }
    __syncthreads();

    // ---- core GEMM: quadrant = (k-half, focal/other); 2 cols per thread ----
    {
        const int wh = qg & 1;
        const int kh = qg >> 1;
        const u64t* W0 = g_Wcore + (size_t)(wh * 125) * H + c0;
        const u64t* W1 = g_Wcore + (size_t)(wh * 125) * H + c1v;
        u64t a0[8], a1[8];
        #pragma unroll
        for (int e = 0; e < 8; e++) { a0[e] = 0ull; a1[e] = 0ull; }

        int kc = kh ? 64 : 0;
        const int kstop = kh ? 120 : 60;
        u64t wa0[4], wa1[4];
        ldw4(wa0, wa1, W0, W1, kc, H);
        #pragma unroll 1
        for (; kc < kstop; kc += 4) {
            u64t wb0[4], wb1[4];
            ldw4(wb0, wb1, W0, W1, kc + 4, H);
            chunk_body<8>(a0, a1, s1s, HP, 2 * kc, wa0, wa1);
            cpw4(wa0, wa1, wb0, wb1);
        }
        chunk_body<8>(a0, a1, s1s, HP, 2 * kstop, wa0, wa1);
        if (kh) {
            u64t wt0 = W0[(size_t)124 * H], wt1 = W1[(size_t)124 * H];
            #pragma unroll
            for (int e = 0; e < 8; e++) {
                u64t v = *(const u64t*)&s1s[e * HP + 248];
                fma2(a0[e], v, wt0);
                fma2(a1[e], v, wt1);
            }
        }
        float* fd = kh ? (wh ? obufB : fbufB) : (wh ? obufA : fbufA);
        #pragma unroll
        for (int e = 0; e < 8; e++) {
            fd[e * HP + c0] = sum2(a0[e]);
            if (c1ok) fd[e * HP + c1] = sum2(a1[e]);
        }
    }
    __syncthreads();

    // ---- merged assemble + LN stats (warp per pair; division-free) ----
    for (int p = warp; p < NP; p += 16) {
        const int fi = (p * 9363) >> 16;        // p / 7
        const int jj = p - fi * 7;
        const int o = jj + (jj >= fi);
        const float* fA = fbufA + fi * HP;
        const float* fB = fbufB + fi * HP;
        const float* oA = obufA + o * HP;
        const float* oB = obufB + o * HP;
        float s = 0.f, s2 = 0.f;
        for (int c = lane; c < H; c += 32) {
            float v = fmaxf(fA[c] + fB[c] + oA[c] + oB[c] + core_b[c], 0.f);
            coreb[p * HP + c] = v;
            s += v; s2 += v * v;
        }
        #pragma unroll
        for (int off = 16; off; off >>= 1) {
            s  += __shfl_xor_sync(0xffffffffu, s,  off);
            s2 += __shfl_xor_sync(0xffffffffu, s2, off);
        }
        if (lane == 0) {
            float mu = s * (1.f / H);
            float rs = rsqrtf(s2 * (1.f / H) - mu * mu + EPS_);
            stA[2 * p]     = mu * rs;
            stA[2 * p + 1] = rs;
        }
    }
    __syncthreads();

    // ---- ctx GEMM over RAW coreb with folded weights; LN in epilogue ----
    {
        const int pbase = qg * 14;
        const u64t* W0 = g_Wctx + c0;
        const u64t* W1 = g_Wctx + c1v;
        u64t a0[14], a1[14];
        #pragma unroll
        for (int pp = 0; pp < 14; pp++) { a0[pp] = 0ull; a1[pp] = 0ull; }

        u64t wa0[2], wa1[2];
        wa0[0] = W0[0]; wa0[1] = W0[H];
        wa1[0] = W1[0]; wa1[1] = W1[H];
        #pragma unroll 2
        for (int kc2 = 0; kc2 < 122; kc2 += 2) {
            u64t wb0[2], wb1[2];
            wb0[0] = W0[(size_t)(kc2 + 2) * H]; wb0[1] = W0[(size_t)(kc2 + 3) * H];
            wb1[0] = W1[(size_t)(kc2 + 2) * H]; wb1[1] = W1[(size_t)(kc2 + 3) * H];
            const int k = 2 * kc2;
            #pragma unroll
            for (int pp = 0; pp < 14; pp++) {
                ulonglong2 v = *(const ulonglong2*)&coreb[(pbase + pp) * HP + k];
                fma2(a0[pp], v.x, wa0[0]); fma2(a0[pp], v.y, wa0[1]);
                fma2(a1[pp], v.x, wa1[0]); fma2(a1[pp], v.y, wa1[1]);
            }
            wa0[0] = wb0[0]; wa0[1] = wb0[1];
            wa1[0] = wb1[0]; wa1[1] = wb1[1];
        }
        {
            #pragma unroll
            for (int pp = 0; pp < 14; pp++) {
                ulonglong2 v = *(const ulonglong2*)&coreb[(pbase + pp) * HP + 244];
                fma2(a0[pp], v.x, wa0[0]); fma2(a0[pp], v.y, wa0[1]);
                fma2(a1[pp], v.x, wa1[0]); fma2(a1[pp], v.y, wa1[1]);
            }
        }
        {
            u64t wt0 = W0[(size_t)124 * H], wt1 = W1[(size_t)124 * H];
            #pragma unroll
            for (int pp = 0; pp < 14; pp++) {
                u64t v = *(const u64t*)&coreb[(pbase + pp) * HP + 248];
                fma2(a0[pp], v, wt0);
                fma2(a1[pp], v, wt1);
            }
        }
        const float t10 = g_t1c[c0], t20 = g_t2c[c0];
        const float t11 = g_t1c[c1v], t21 = g_t2c[c1v];
        #pragma unroll
        for (int pp = 0; pp < 14; pp++) {
            const int p = pbase + pp;
            const float ms = stA[2 * p], rs = stA[2 * p + 1];
            ctxb[p * HP + c0] = fmaxf(rs * sum2(a0[pp]) - ms * t20 + t10, 0.f);
            if (c1ok)
                ctxb[p * HP + c1] = fmaxf(rs * sum2(a1[pp]) - ms * t21 + t11, 0.f);
        }
    }

    // ---- att1 GEMM over RAW coreb (folded); 8 groups x 7 pairs x 2 cols ----
    {
        const int g8 = t >> 6, u6 = t & 63;
        if (u6 < 50) {
            const int pbase = g8 * 7;
            const int ac0 = u6, ac1 = u6 + 50;
            const u64t* W0 = g_Watt + ac0;
            const u64t* W1 = g_Watt + ac1;
            u64t a0[7], a1[7];
            #pragma unroll
            for (int pp = 0; pp < 7; pp++) { a0[pp] = 0ull; a1[pp] = 0ull; }

            u64t wa0[4], wa1[4];
            ldw4(wa0, wa1, W0, W1, 0, HA_);
            #pragma unroll 2
            for (int kc = 0; kc < 120; kc += 4) {
                u64t wb0[4], wb1[4];
                ldw4(wb0, wb1, W0, W1, kc + 4, HA_);
                chunk_body<7>(a0, a1, coreb + pbase * HP, HP, 2 * kc, wa0, wa1);
                cpw4(wa0, wa1, wb0, wb1);
            }
            chunk_body<7>(a0, a1, coreb + pbase * HP, HP, 240, wa0, wa1);
            {
                u64t wt0 = W0[(size_t)124 * HA_], wt1 = W1[(size_t)124 * HA_];
                #pragma unroll
                for (int pp = 0; pp < 7; pp++) {
                    u64t v = *(const u64t*)&coreb[(pbase + pp) * HP + 248];
                    fma2(a0[pp], v, wt0);
                    fma2(a1[pp], v, wt1);
                }
            }
            const float t10 = g_t1a[ac0], t20 = g_t2a[ac0];
            const float t11 = g_t1a[ac1], t21 = g_t2a[ac1];
            #pragma unroll
            for (int pp = 0; pp < 7; pp++) {
                const int p = pbase + pp;
                const float ms = stA[2 * p], rs = stA[2 * p + 1];
                attb[p * HA_ + ac0] = tanhf(rs * sum2(a0[pp]) - ms * t20 + t10);
                attb[p * HA_ + ac1] = tanhf(rs * sum2(a1[pp]) - ms * t21 + t11);
            }
        }
    }
    __syncthreads();

    // ---- ctx LN stats + att single-pass (folded att-LN) + sigmoid ----
    const float Sgw = g_Sgw, Sbw = g_Sbw;
    for (int p = warp; p < NP; p += 16) {
        {
            float s = 0.f, s2 = 0.f;
            for (int k = lane; k < H; k += 32) {
                float v = ctxb[p * HP + k];
                s += v; s2 += v * v;
            }
            #pragma unroll
            for (int off = 16; off; off >>= 1) {
                s  += __shfl_xor_sync(0xffffffffu, s,  off);
                s2 += __shfl_xor_sync(0xffffffffu, s2, off);
            }
            if (lane == 0) {
                float mu = s * (1.f / H);
                float rs = rsqrtf(s2 * (1.f / H) - mu * mu + EPS_);
                stC[2 * p]     = mu * rs;
                stC[2 * p + 1] = rs;
            }
        }
        {   // single pass: Σv, Σv², Σv·gw2
            float s = 0.f, s2 = 0.f, sd = 0.f;
            for (int k = lane; k < HA_; k += 32) {
                float v = attb[p * HA_ + k];
                s += v; s2 += v * v; sd += v * g_gw2[k];
            }
            #pragma unroll
            for (int off = 16; off; off >>= 1) {
                s  += __shfl_xor_sync(0xffffffffu, s,  off);
                s2 += __shfl_xor_sync(0xffffffffu, s2, off);
                sd += __shfl_xor_sync(0xffffffffu, sd, off);
            }
            if (lane == 0) {
                float mu = s * (1.f / HA_);
                float rs = rsqrtf(s2 * (1.f / HA_) - mu * mu + EPS_);
                float s3 = rs * sd - mu * rs * Sgw + Sbw;
                attv[p] = 1.f / (1.f + expf(-(s3 + att_b2[0])));
            }
        }
    }
    __syncthreads();

    // ---- effect (folded ctx-LN) ----
    {
        const int c = t & 255, eh = t >> 8;
        if (c < H) {
            const float cgc = ctx_g[c], cbtc = ctx_bt[c];
            #pragma unroll
            for (int e4 = 0; e4 < 4; e4++) {
                const int e = eh * 4 + e4;
                float acc = 0.f, A = 0.f, Bs = 0.f;
                #pragma unroll
                for (int j = 0; j < 7; j++) {
                    const int p = e * 7 + j;
                    const float av = attv[p];
                    const float w  = av * stC[2 * p + 1];
                    acc += w * ctxb[p * HP + c];
                    A   += av;
                    Bs  += av * stC[2 * p];
                }
                g_eff[((size_t)grp * KK + e) * H + c] = cgc * (acc - Bs) + A * cbtc;
            }
        }
    }
}

// ---------------------------------------------------------------------------
// Kernel 3: out GEMM via tf32 mma.sync (3xTF32), concat fused into A-load.
// ---------------------------------------------------------------------------
__device__ __forceinline__ float load_tot(const float* __restrict__ x, int row, int k) {
    if (k < H)          return g_s1[(size_t)row * H + k];
    if (k < 2 * H)      return g_eff[(size_t)row * H + (k - H)];
    if (k < CIN)        return x[(size_t)row * MM + (k - 2 * H)];
    return 0.f;
}

#define LOAD_STAGE(s, k0) do {                                                        \
    {   /* A: gather [s1|eff|x] + tf32 hi/lo split in-register */                     \
        const int row = m0 + am;                                                      \
        float v0 = load_tot(x, row, (k0) + ak);                                       \
        float v1 = load_tot(x, row, (k0) + ak + 1);                                   \
        float h0 = tf32r(v0), h1 = tf32r(v1);                                         \
        AsH[s][am * 8 + ak]     = h0;                                                 \
        AsH[s][am * 8 + ak + 1] = h1;                                                 \
        AsL[s][am * 8 + ak]     = tf32r(v0 - h0);                                     \
        AsL[s][am * 8 + ak + 1] = tf32r(v1 - h1);                                     \
    }                                                                                 \
    {   /* B: precomputed hi/lo planes */                                             \
        const float* wh = &g_WHp[(size_t)((k0) + bk) * NPAD2 + bn];                   \
        const float* wl = &g_WLp[(size_t)((k0) + bk) * NPAD2 + bn];                   \
        *(float4*)&BsH[s][bk * 260 + bn]     = *(const float4*)wh;                    \
        *(float4*)&BsH[s][bk * 260 + bn + 4] = *(const float4*)(wh + 4);              \
        *(float4*)&BsL[s][bk * 260 + bn]     = *(const float4*)wl;                    \
        *(float4*)&BsL[s][bk * 260 + bn + 4] = *(const float4*)(wl + 4);              \
    }                                                                                 \
} while (0)

__global__ __launch_bounds__(256, 2) void out_mma_kernel(
    const float* __restrict__ x,
    const float* __restrict__ bias, float* __restrict__ out)
{
    __shared__ float AsH[2][64 * 8], AsL[2][64 * 8];
    __shared__ float BsH[2][8 * 260], BsL[2][8 * 260];

    const int t = threadIdx.x;
    const int m0 = blockIdx.x * 64;
    const int w = t >> 5, lane = t & 31;
    const int wm = w & 1, wn = w >> 1;
    const int gid = lane >> 2, ctid = lane & 3;

    const int am = t >> 2;              // A row 0..63
    const int ak = (t & 3) * 2;         // A k-pair within 8
    const int bk = t >> 5;              // B k row 0..7
    const int bn = (t & 31) * 8;        // B n 0..248

    float d[2][8][4];
    #pragma unroll
    for (int mf = 0; mf < 2; mf++)
        #pragma unroll
        for (int nf = 0; nf < 8; nf++)
            #pragma unroll
            for (int q = 0; q < 4; q++) d[mf][nf][q] = 0.f;

    LOAD_STAGE(0, 0);

    #pragma unroll 1
    for (int ks = 0; ks < 135; ks++) {
        const int s = ks & 1;
        __syncthreads();
        if (ks + 1 < 135) LOAD_STAGE(s ^ 1, (ks + 1) * 8);

        unsigned aH[2][4], aL[2][4];
        #pragma unroll
        for (int mf = 0; mf < 2; mf++) {
            const int rb = wm * 32 + mf * 16;
            aH[mf][0] = __float_as_uint(AsH[s][(rb + gid) * 8 + ctid]);
            aH[mf][1] = __float_as_uint(AsH[s][(rb + gid + 8) * 8 + ctid]);
            aH[mf][2] = __float_as_uint(AsH[s][(rb + gid) * 8 + ctid + 4]);
            aH[mf][3] = __float_as_uint(AsH[s][(rb + gid + 8) * 8 + ctid + 4]);
            aL[mf][0] = __float_as_uint(AsL[s][(rb + gid) * 8 + ctid]);
            aL[mf][1] = __float_as_uint(AsL[s][(rb + gid + 8) * 8 + ctid]);
            aL[mf][2] = __float_as_uint(AsL[s][(rb + gid) * 8 + ctid + 4]);
            aL[mf][3] = __float_as_uint(AsL[s][(rb + gid + 8) * 8 + ctid + 4]);
        }
        #pragma unroll
        for (int nf = 0; nf < 8; nf++) {
            const int n = wn * 64 + nf * 8 + gid;
            unsigned bH0 = __float_as_uint(BsH[s][ctid * 260 + n]);
            unsigned bH1 = __float_as_uint(BsH[s][(ctid + 4) * 260 + n]);
            unsigned bL0 = __float_as_uint(BsL[s][ctid * 260 + n]);
            unsigned bL1 = __float_as_uint(BsL[s][(ctid + 4) * 260 + n]);
            #pragma unroll
            for (int mf = 0; mf < 2; mf++) {
                MMA_TF32(d[mf][nf], aH[mf], bH0, bH1);
                MMA_TF32(d[mf][nf], aL[mf], bH0, bH1);
                MMA_TF32(d[mf][nf], aH[mf], bL0, bL1);
            }
        }
    }

    #pragma unroll
    for (int mf = 0; mf < 2; mf++) {
        const int r0 = m0 + wm * 32 + mf * 16 + gid;
        #pragma unroll
        for (int nf = 0; nf < 8; nf++) {
            const int n = wn * 64 + nf * 8 + 2 * ctid;
            if (n < H) {
                float b0 = bias[n], b1 = bias[n + 1];
                out[(size_t)r0 * H + n]           = d[mf][nf][0] + b0;
                out[(size_t)r0 * H + n + 1]       = d[mf][nf][1] + b1;
                out[(size_t)(r0 + 8) * H + n]     = d[mf][nf][2] + b0;
                out[(size_t)(r0 + 8) * H + n + 1] = d[mf][nf][3] + b1;
            }
        }
    }
}

// ---------------------------------------------------------------------------
extern "C" void kernel_launch(void* const* d_in, const int* in_sizes, int n_in,
                              void* d_out, int out_size)
{
    const float* x       = (const float*)d_in[0];
    const float* state   = (const float*)d_in[1];
    const float* enc_W   = (const float*)d_in[2];
    const float* enc_b   = (const float*)d_in[3];
    const float* enc_g   = (const float*)d_in[4];
    const float* enc_bt  = (const float*)d_in[5];
    const float* core_W  = (const float*)d_in[6];
    const float* core_b  = (const float*)d_in[7];
    const float* core_g  = (const float*)d_in[8];
    const float* core_bt = (const float*)d_in[9];
    const float* ctx_W   = (const float*)d_in[10];
    const float* ctx_b   = (const float*)d_in[11];
    const float* ctx_g   = (const float*)d_in[12];
    const float* ctx_bt  = (const float*)d_in[13];
    const float* att_W1  = (const float*)d_in[14];
    const float* att_b1  = (const float*)d_in[15];
    const float* att_g   = (const float*)d_in[16];
    const float* att_bt  = (const float*)d_in[17];
    const float* att_W2  = (const float*)d_in[18];
    const float* att_b2  = (const float*)d_in[19];
    const float* out_W   = (const float*)d_in[20];
    const float* out_b   = (const float*)d_in[21];
    float* out = (float*)d_out;

    static int configured = 0;
    const int pair_smB = (5 * KK * HP + 2 * NP * HP + NP * HA_ + NP + 4 * NP) * (int)sizeof(float);
    if (!configured) {
        cudaFuncSetAttribute(pair_kernel, cudaFuncAttributeMaxDynamicSharedMemorySize, pair_smB);
        configured = 1;
    }

    prep_all<<<(N_PREP + 255) / 256, 256>>>(enc_W, core_W, ctx_W, att_W1, out_W,
                                            core_g, core_bt, ctx_b, att_b1,
                                            att_g, att_bt, att_W2);
    enc_kernel<<<BK / ER, 512>>>(state, enc_b, enc_g, enc_bt);
    pair_kernel<<<NB, 512, pair_smB>>>(core_b, ctx_g, ctx_bt, att_b2);
    out_mma_kernel<<<BK / 64, 256>>>(x, out_b, out);
}